// round 7
// baseline (speedup 1.0000x reference)
#include <cuda_runtime.h>

#define NBATCH 16
#define NPT    4096
#define NQ     1024
#define NSAMP  32
#define NCHUNK 4
#define QCH    (NQ/NCHUNK)                 // 256 samples per chunk
#define REGION (NBATCH*QCH*NSAMP)          // entries per chunk region
#define OUT1SZ (NBATCH*3*NQ)               // 49152
#define OUT2SZ (NBATCH*128*NQ)             // 2097152
#define FULLM  0xffffffffu

__device__ int      g_fps[NBATCH*NQ];
__device__ int      g_prog[NBATCH];        // FPS progress (samples published)
__device__ unsigned g_ent[NCHUNK*REGION];
__device__ int      g_ecnt4[NCHUNK];
__device__ float    g_W0[67*64];           // [c][o] folded BN
__device__ float    g_B0[64];
__device__ float    g_W1[64*64];           // [c][o]
__device__ float    g_B1[64];
__device__ float    g_W2[64*128];          // [k][o]
__device__ float    g_B2[128];

// ---- f32x2 packed helpers: two independent .rn fp32 ops per instruction --
__device__ __forceinline__ unsigned long long pk2(float a, float b){
    unsigned long long r; asm("mov.b64 %0,{%1,%2};":"=l"(r):"f"(a),"f"(b)); return r;
}
__device__ __forceinline__ void upk2(unsigned long long v, float&a, float&b){
    asm("mov.b64 {%0,%1},%2;":"=f"(a),"=f"(b):"l"(v));
}
__device__ __forceinline__ unsigned long long add2(unsigned long long a, unsigned long long b){
    unsigned long long r; asm("add.rn.f32x2 %0,%1,%2;":"=l"(r):"l"(a),"l"(b)); return r;
}
__device__ __forceinline__ unsigned long long mul2(unsigned long long a, unsigned long long b){
    unsigned long long r; asm("mul.rn.f32x2 %0,%1,%2;":"=l"(r):"l"(a),"l"(b)); return r;
}

// ---------------- zero progress flags (must precede fork) ----------------
__global__ void zero_prog_kernel(){
    if (threadIdx.x < NBATCH) g_prog[threadIdx.x] = 0;
    __threadfence();
}

// ---------------- prep: zero out2, fold BN into weights, reset counters ---
__global__ void prep_kernel(float* __restrict__ out2,
    const float* w0,const float* b0,const float* g0,const float* be0,const float* m0,const float* v0,
    const float* w1,const float* b1,const float* g1,const float* be1,const float* m1,const float* v1,
    const float* w2,const float* b2,const float* g2,const float* be2,const float* m2,const float* v2)
{
    int idx = blockIdx.x*blockDim.x + threadIdx.x;
    if (idx < OUT2SZ/4) ((float4*)out2)[idx] = make_float4(0.f,0.f,0.f,0.f);
    if (blockIdx.x == 0) {
        int t = threadIdx.x;
        if (t < NCHUNK) g_ecnt4[t] = 0;
        for (int i=t;i<67*64;i+=blockDim.x){int c=i>>6,o=i&63;float s=g0[o]*rsqrtf(v0[o]+1e-5f);g_W0[i]=w0[o*67+c]*s;}
        for (int i=t;i<64*64;i+=blockDim.x){int c=i>>6,o=i&63;float s=g1[o]*rsqrtf(v1[o]+1e-5f);g_W1[i]=w1[o*64+c]*s;}
        for (int i=t;i<64*128;i+=blockDim.x){int k=i>>7,o=i&127;float s=g2[o]*rsqrtf(v2[o]+1e-5f);g_W2[i]=w2[o*64+k]*s;}
        if (t<64){float s=g0[t]*rsqrtf(v0[t]+1e-5f);g_B0[t]=(b0[t]-m0[t])*s+be0[t];}
        if (t<64){float s=g1[t]*rsqrtf(v1[t]+1e-5f);g_B1[t]=(b1[t]-m1[t])*s+be1[t];}
        if (t<128){float s=g2[t]*rsqrtf(v2[t]+1e-5f);g_B2[t]=(b2[t]-m2[t])*s+be2[t];}
    }
}

// ---------------- FPS: monolithic, publishes g_fps + out1, release fence --
__global__ void __launch_bounds__(512,1) fps_kernel(const float* __restrict__ xyz,
                                                    float* __restrict__ out1)
{
    __shared__ unsigned s_v[2][16], s_ix[2][16];
    int b = blockIdx.x, t = threadIdx.x;
    int lane = t & 31, wid = t >> 5;
    const float* X = xyz + b*3*NPT;
    int base = t*8;
    float px[8],py[8],pz[8],dd[8];
    {
        float4 a0 = *(const float4*)(X + base);
        float4 a1 = *(const float4*)(X + base + 4);
        float4 b0 = *(const float4*)(X + NPT + base);
        float4 b1 = *(const float4*)(X + NPT + base + 4);
        float4 c0 = *(const float4*)(X + 2*NPT + base);
        float4 c1 = *(const float4*)(X + 2*NPT + base + 4);
        px[0]=a0.x;px[1]=a0.y;px[2]=a0.z;px[3]=a0.w;px[4]=a1.x;px[5]=a1.y;px[6]=a1.z;px[7]=a1.w;
        py[0]=b0.x;py[1]=b0.y;py[2]=b0.z;py[3]=b0.w;py[4]=b1.x;py[5]=b1.y;py[6]=b1.z;py[7]=b1.w;
        pz[0]=c0.x;pz[1]=c0.y;pz[2]=c0.z;pz[3]=c0.w;pz[4]=c1.x;pz[5]=c1.y;pz[6]=c1.z;pz[7]=c1.w;
    }
    unsigned long long px2[4],py2[4],pz2[4];
    #pragma unroll
    for (int p=0;p<4;p++){ px2[p]=pk2(px[2*p],px[2*p+1]); py2[p]=pk2(py[2*p],py[2*p+1]); pz2[p]=pk2(pz[2*p],pz[2*p+1]); }
    #pragma unroll
    for (int j=0;j<8;j++) dd[j]=1e10f;
    int f = 0;
    float cx=__ldg(X), cy=__ldg(X+NPT), cz=__ldg(X+2*NPT);
    for (int it=0; it<NQ; ++it) {
        if (t == 0){   // publish sample it (index + new_xyz coords)
            g_fps[b*NQ+it] = f;
            out1[b*3072 + it]        = cx;
            out1[b*3072 + NQ  + it]  = cy;
            out1[b*3072 + 2*NQ + it] = cz;
        }
        unsigned long long ncx=pk2(-cx,-cx), ncy=pk2(-cy,-cy), ncz=pk2(-cz,-cz);
        #pragma unroll
        for (int p=0;p<4;p++){
            // (px-cx)^2+(py-cy)^2+(pz-cz)^2, each op .rn, left-assoc (matches XLA)
            unsigned long long dx=add2(px2[p],ncx), dy=add2(py2[p],ncy), dz=add2(pz2[p],ncz);
            unsigned long long d2=add2(add2(mul2(dx,dx),mul2(dy,dy)),mul2(dz,dz));
            float dlo,dhi; upk2(d2,dlo,dhi);
            dd[2*p]   = fminf(dd[2*p],   dlo);
            dd[2*p+1] = fminf(dd[2*p+1], dhi);
        }
        float best = dd[0]; int bidx = base;
        #pragma unroll
        for (int j=1;j<8;j++) if (dd[j] > best){ best=dd[j]; bidx=base+j; }
        unsigned db   = __float_as_uint(best);        // >=0: uint order == float order
        unsigned wmax = __reduce_max_sync(FULLM, db);
        unsigned mk   = __ballot_sync(FULLM, db==wmax);
        int src = __ffs(mk)-1;                         // lowest lane = lowest index
        int par = it & 1;
        if (db==wmax && lane==src){                    // winner lane writes directly
            s_v[par][wid]=wmax; s_ix[par][wid]=(unsigned)bidx;
        }
        __syncthreads();
        unsigned vm   = s_v[par][lane & 15];
        unsigned bmax = __reduce_max_sync(FULLM, vm);
        unsigned mk2  = __ballot_sync(FULLM, vm==bmax);
        int src2 = __ffs(mk2)-1;                       // lowest warp = lowest index
        f = (int)s_ix[par][src2];
        cx=__ldg(X+f); cy=__ldg(X+NPT+f); cz=__ldg(X+2*NPT+f);   // broadcast L1 hit
        if (t==0 && (it&31)==31){
            __threadfence();                           // release all prior publishes
            ((volatile int*)g_prog)[b] = it+1;
        }
    }
}

// ---------------- ball query chunk: spins on progress, reads g_fps+xyz ----
__global__ void __launch_bounds__(256) bq_kernel(const float* __restrict__ xyz, int ck)
{
    __shared__ unsigned ebuf[8*128];
    int b = blockIdx.x >> 3, qb = blockIdx.x & 7;
    // wait until FPS has published this CTA's 32 samples (no silent fallback)
    int thr = ck*QCH + qb*32 + 32;
    if (threadIdx.x == 0){
        long long guard = 0;
        while (((volatile int*)g_prog)[b] < thr && guard < 20000000LL){ __nanosleep(128); ++guard; }
    }
    __syncthreads();    // CTA-wide fence: g_prog acquire covers the reads below
    const float* Xx = xyz + b*3*NPT;
    const float* Xy = Xx + NPT;
    const float* Xz = Xx + 2*NPT;
    int wid = threadIdx.x>>5, lane = threadIdx.x&31;
    unsigned lt = (1u<<lane)-1u;
    unsigned* wbuf = ebuf + wid*128;
    int s0 = ck*QCH + qb*32 + wid*4;
    float cx[4],cy[4],cz[4]; int cnt[4]={0,0,0,0}; unsigned gtag[4];
    #pragma unroll
    for (int q=0;q<4;q++){
        int s = s0+q;
        int ci = ((volatile const int*)g_fps)[b*NQ+s];   // L2-coherent index read
        cx[q]=__ldg(Xx+ci); cy[q]=__ldg(Xy+ci); cz[q]=__ldg(Xz+ci);  // immutable input
        gtag[q]=(unsigned)(b*NQ+s)<<12;
    }
    int wn = 0;
    for (int bp=0; bp<NPT; bp+=128){
        if (cnt[0]>=NSAMP && cnt[1]>=NSAMP && cnt[2]>=NSAMP && cnt[3]>=NSAMP) break;
        int p = bp + lane*4;
        float4 fx = __ldg((const float4*)(Xx+p));
        float4 fy = __ldg((const float4*)(Xy+p));
        float4 fz = __ldg((const float4*)(Xz+p));
        float pxl[4]={fx.x,fx.y,fx.z,fx.w};
        float pyl[4]={fy.x,fy.y,fy.z,fy.w};
        float pzl[4]={fz.x,fz.y,fz.z,fz.w};
        #pragma unroll
        for (int q=0;q<4;q++){
            if (cnt[q]>=NSAMP) continue;          // warp-uniform
            bool inb[4]; unsigned m[4];
            #pragma unroll
            for (int j=0;j<4;j++){
                float dx=pxl[j]-cx[q], dy=pyl[j]-cy[q], dz=pzl[j]-cz[q];
                float d2=__fadd_rn(__fadd_rn(__fmul_rn(dx,dx),__fmul_rn(dy,dy)),__fmul_rn(dz,dz));
                inb[j] = (d2 <= 0.04f);
                m[j] = __ballot_sync(FULLM, inb[j]);
            }
            int tot = __popc(m[0])+__popc(m[1])+__popc(m[2])+__popc(m[3]);
            if (!tot) continue;                    // warp-uniform
            if (cnt[q] + tot <= NSAMP){
                int off = wn;                      // order irrelevant downstream
                #pragma unroll
                for (int j=0;j<4;j++){
                    if (inb[j]) wbuf[off + __popc(m[j]&lt)] = gtag[q] | (unsigned)(p+j);
                    off += __popc(m[j]);
                }
                wn += tot; cnt[q] += tot;
            } else {
                // rare: crossing NSAMP — redo this 128-chunk in index order
                for (int sub=0; sub<4 && cnt[q]<NSAMP; ++sub){
                    int pp = bp + sub*32 + lane;
                    float dx=__ldg(Xx+pp)-cx[q], dy=__ldg(Xy+pp)-cy[q], dz=__ldg(Xz+pp)-cz[q];
                    float d2=__fadd_rn(__fadd_rn(__fmul_rn(dx,dx),__fmul_rn(dy,dy)),__fmul_rn(dz,dz));
                    bool in = (d2 <= 0.04f);
                    unsigned mask = __ballot_sync(FULLM, in);
                    int pc = __popc(mask);
                    int take = min(pc, NSAMP-cnt[q]);
                    if (in){
                        int pos = __popc(mask & lt);
                        if (pos < take) wbuf[wn+pos] = gtag[q] | (unsigned)pp;
                    }
                    wn += take; cnt[q] += take;
                }
            }
        }
    }
    int gb = 0;
    if (lane==0) gb = atomicAdd(&g_ecnt4[ck], wn);
    gb = __shfl_sync(FULLM, gb, 0);
    unsigned* reg = g_ent + ck*REGION;
    for (int i=lane;i<wn;i+=32) reg[gb+i] = wbuf[i];
}

// ---------------- fused 3-layer MLP chunk + max scatter ------------------
// Reads g_fps + xyz for the centroid (no out1 dependency at all).
__global__ void __launch_bounds__(256,3) mlp_kernel(const float* __restrict__ xyz,
                                                    const float* __restrict__ pts,
                                                    float* __restrict__ out2, int ck)
{
    extern __shared__ float sm[];
    float* sX  = sm;            // 67*64 = 4288
    float* sH  = sm + 4288;     // 64*64 = 4096
    float* sB0 = sm + 8384;     // 64
    float* sB1 = sm + 8448;     // 64
    float* sB2 = sm + 8512;     // 128  (total 8640 floats = 34560 B)
    int t = threadIdx.x;
    if (t<64){ sB0[t]=g_B0[t]; sB1[t]=g_B1[t]; }
    if (t<128) sB2[t]=g_B2[t];
    const unsigned* ent = g_ent + ck*REGION;
    int E = g_ecnt4[ck];
    int tiles = (E+63)>>6;
    int tx = t&15, ty = t>>4;
    int* outI = (int*)out2;
    int le = t>>2, sub = t&3;
    for (int tb = blockIdx.x; tb < tiles; tb += gridDim.x){
        int tbase = tb<<6;
        __syncthreads();
        {   // gather 67-channel input for 64 entries (4 threads / entry)
            int ge = tbase + le;
            unsigned raw = ent[ge < E ? ge : 0] & 0x3FFFFFFu;
            int p = raw & 4095; int g = raw >> 12; int bb = g >> 10, s = g & 1023;
            int ci = ((volatile const int*)g_fps)[g];          // centroid index
            const float* pc = pts  + (size_t)(bb*64)*NPT + p;
            const float* xc = xyz  + (size_t)(bb*3)*NPT;
            for (int c=sub;c<67;c+=4){
                float v;
                if (c<3) v = __ldg(xc + c*NPT + p) - __ldg(xc + c*NPT + ci);
                else     v = __ldg(pc + (c-3)*NPT);
                sX[c*64+le] = v;
            }
        }
        __syncthreads();
        // ---- layer 0: 67 -> 64 ----
        float acc[4][4];
        #pragma unroll
        for (int j=0;j<4;j++){ float bb=sB0[ty*4+j];
            #pragma unroll
            for (int i=0;i<4;i++) acc[i][j]=bb; }
        #pragma unroll 4
        for (int k=0;k<67;k++){
            float4 xv = *(const float4*)&sX[k*64+tx*4];
            float4 wv = __ldg((const float4*)&g_W0[k*64+ty*4]);
            float xr[4]={xv.x,xv.y,xv.z,xv.w};
            float wr[4]={wv.x,wv.y,wv.z,wv.w};
            #pragma unroll
            for (int i=0;i<4;i++)
                #pragma unroll
                for (int j=0;j<4;j++) acc[i][j] = fmaf(xr[i],wr[j],acc[i][j]);
        }
        #pragma unroll
        for (int j=0;j<4;j++){
            float4 hv = make_float4(fmaxf(acc[0][j],0.f),fmaxf(acc[1][j],0.f),
                                    fmaxf(acc[2][j],0.f),fmaxf(acc[3][j],0.f));
            *(float4*)&sH[(ty*4+j)*64 + tx*4] = hv;
        }
        __syncthreads();
        // ---- layer 1: 64 -> 64 ----
        #pragma unroll
        for (int j=0;j<4;j++){ float bb=sB1[ty*4+j];
            #pragma unroll
            for (int i=0;i<4;i++) acc[i][j]=bb; }
        #pragma unroll 4
        for (int k=0;k<64;k++){
            float4 xv = *(const float4*)&sH[k*64+tx*4];
            float4 wv = __ldg((const float4*)&g_W1[k*64+ty*4]);
            float xr[4]={xv.x,xv.y,xv.z,xv.w};
            float wr[4]={wv.x,wv.y,wv.z,wv.w};
            #pragma unroll
            for (int i=0;i<4;i++)
                #pragma unroll
                for (int j=0;j<4;j++) acc[i][j] = fmaf(xr[i],wr[j],acc[i][j]);
        }
        #pragma unroll
        for (int j=0;j<4;j++){
            float4 hv = make_float4(fmaxf(acc[0][j],0.f),fmaxf(acc[1][j],0.f),
                                    fmaxf(acc[2][j],0.f),fmaxf(acc[3][j],0.f));
            *(float4*)&sX[(ty*4+j)*64 + tx*4] = hv;
        }
        __syncthreads();
        // ---- layer 2: 64 -> 128 + relu + merged atomicMax scatter ----
        float a2[4][8];
        #pragma unroll
        for (int j=0;j<8;j++){ float bb=sB2[ty*8+j];
            #pragma unroll
            for (int i=0;i<4;i++) a2[i][j]=bb; }
        #pragma unroll 2
        for (int k=0;k<64;k++){
            float4 xv = *(const float4*)&sX[k*64+tx*4];
            float4 wa = __ldg((const float4*)&g_W2[k*128+ty*8]);
            float4 wb = __ldg((const float4*)&g_W2[k*128+ty*8+4]);
            float xr[4]={xv.x,xv.y,xv.z,xv.w};
            float wr[8]={wa.x,wa.y,wa.z,wa.w,wb.x,wb.y,wb.z,wb.w};
            #pragma unroll
            for (int i=0;i<4;i++)
                #pragma unroll
                for (int j=0;j<8;j++) a2[i][j]=fmaf(xr[i],wr[j],a2[i][j]);
        }
        unsigned gid[4];
        #pragma unroll
        for (int i=0;i<4;i++){
            int ge = tbase + tx*4 + i;
            gid[i] = (ge < E) ? ((ent[ge] >> 12) & 0x3FFFu) : 0xFFFFFFFFu;
        }
        #pragma unroll
        for (int i=0;i<4;i++){
            if (gid[i]==0xFFFFFFFFu) continue;
            if (i>0 && gid[i]==gid[i-1]) continue;
            float mv[8];
            #pragma unroll
            for (int j=0;j<8;j++) mv[j]=a2[i][j];
            #pragma unroll
            for (int i2=1;i2<4;i2++){
                if (i+i2<4 && gid[i+i2]==gid[i]){
                    #pragma unroll
                    for (int j=0;j<8;j++) mv[j]=fmaxf(mv[j],a2[i+i2][j]);
                }
            }
            int bb = gid[i]>>10, s = gid[i]&1023;
            int* po = outI + (bb*128 + ty*8)*NQ + s;
            #pragma unroll
            for (int j=0;j<8;j++)
                atomicMax(po + j*NQ, __float_as_int(fmaxf(mv[j],0.f)));
        }
    }
}

extern "C" void kernel_launch(void* const* d_in, const int* in_sizes, int n_in,
                              void* d_out, int out_size)
{
    const float* xyz = (const float*)d_in[0];
    const float* pts = (const float*)d_in[1];
    float* out1 = (float*)d_out;
    float* out2 = out1 + OUT1SZ;

    static cudaStream_t s2 = nullptr;
    static cudaEvent_t evRoot, evEnd;
    if (!s2){
        cudaStreamCreateWithFlags(&s2, cudaStreamNonBlocking);
        cudaEventCreateWithFlags(&evRoot, cudaEventDisableTiming);
        cudaEventCreateWithFlags(&evEnd, cudaEventDisableTiming);
    }

    // main stream: reset progress flags, then fork the side stream
    zero_prog_kernel<<<1,32>>>();
    cudaEventRecord(evRoot, 0);
    cudaStreamWaitEvent(s2, evRoot, 0);

    // main stream: monolithic FPS (publishes progress as it goes)
    fps_kernel<<<16,512>>>(xyz, out1);

    // side stream: prep, then bq_k (spins on progress) -> mlp_k
    prep_kernel<<<2048,256,0,s2>>>(out2,
        (const float*)d_in[2],(const float*)d_in[3],(const float*)d_in[4],
        (const float*)d_in[5],(const float*)d_in[6],(const float*)d_in[7],
        (const float*)d_in[8],(const float*)d_in[9],(const float*)d_in[10],
        (const float*)d_in[11],(const float*)d_in[12],(const float*)d_in[13],
        (const float*)d_in[14],(const float*)d_in[15],(const float*)d_in[16],
        (const float*)d_in[17],(const float*)d_in[18],(const float*)d_in[19]);
    for (int k=0;k<NCHUNK;k++){
        bq_kernel<<<128,256,0,s2>>>(xyz, k);
        mlp_kernel<<<296,256,34560,s2>>>(xyz, pts, out2, k);
    }

    // join side stream back into the main stream
    cudaEventRecord(evEnd, s2);
    cudaStreamWaitEvent(0, evEnd, 0);
}

// round 9
// speedup vs baseline: 1.0010x; 1.0010x over previous
#include <cuda_runtime.h>

#define NBATCH 16
#define NPT    4096
#define NQ     1024
#define NSAMP  32
#define NCHUNK 4
#define QCH    256
#define REGION (NBATCH*QCH*NSAMP)
#define OUT1SZ (NBATCH*3*NQ)
#define OUT2SZ (NBATCH*128*NQ)
#define FULLM  0xffffffffu
#define NFPS   16
#define NWORK  132
#define NITEM  (NCHUNK*NBATCH*8)   // 512 bq items

__device__ int      g_fps[NBATCH*NQ];
__device__ int      g_prog[NBATCH];
__device__ unsigned g_ent[NCHUNK*REGION];
__device__ int      g_ecnt4[NCHUNK];
__device__ int      g_bqdone[NCHUNK];
__device__ int      g_mlp_ctr[NCHUNK];
__device__ int      g_bq_ctr;
__device__ int      g_zero_ctr;
__device__ int      g_wready;
__device__ float    g_W0[67*64], g_B0[64];
__device__ float    g_W1[64*64], g_B1[64];
__device__ float    g_W2[64*128], g_B2[128];

// ---- f32x2 packed helpers: two independent .rn fp32 ops per instruction --
__device__ __forceinline__ unsigned long long pk2(float a, float b){
    unsigned long long r; asm("mov.b64 %0,{%1,%2};":"=l"(r):"f"(a),"f"(b)); return r;
}
__device__ __forceinline__ void upk2(unsigned long long v, float&a, float&b){
    asm("mov.b64 {%0,%1},%2;":"=f"(a),"=f"(b):"l"(v));
}
__device__ __forceinline__ unsigned long long add2(unsigned long long a, unsigned long long b){
    unsigned long long r; asm("add.rn.f32x2 %0,%1,%2;":"=l"(r):"l"(a),"l"(b)); return r;
}
__device__ __forceinline__ unsigned long long mul2(unsigned long long a, unsigned long long b){
    unsigned long long r; asm("mul.rn.f32x2 %0,%1,%2;":"=l"(r):"l"(a),"l"(b)); return r;
}
__device__ __forceinline__ void spin_ge(const int* p, int thr){
    long long g=0;
    while (*(volatile const int*)p < thr && g < 40000000LL){ __nanosleep(128); ++g; }
}
#define HBAR(id) asm volatile("bar.sync %0, 256;" :: "r"(id) : "memory")

// ---------------- reset (separate launch, precedes fused kernel) ----------
__global__ void reset_kernel(){
    int t = threadIdx.x;
    if (t < NBATCH) g_prog[t] = 0;
    if (t < NCHUNK){ g_ecnt4[t]=0; g_bqdone[t]=0; g_mlp_ctr[t]=0; }
    if (t == 0){ g_bq_ctr=0; g_zero_ctr=0; g_wready=0; }
    __threadfence();
}

// ---------------- fused persistent kernel: 16 fps CTAs + 132 workers ------
__global__ void __launch_bounds__(512,1) fused_kernel(
    const float* __restrict__ xyz, const float* __restrict__ pts,
    float* __restrict__ out1, float* __restrict__ out2,
    const float* w0,const float* b0,const float* g0,const float* be0,const float* m0,const float* v0,
    const float* w1,const float* b1,const float* g1,const float* be1,const float* m1,const float* v1,
    const float* w2,const float* b2,const float* g2,const float* be2,const float* m2,const float* v2)
{
    __shared__ __align__(16) unsigned s_v[2][16], s_ix[2][16];
    __shared__ __align__(16) unsigned ebuf[16][128];
    __shared__ __align__(16) int s_item[2];
    __shared__ int s_tl;
    __shared__ __align__(16) float sB0[64], sB1[64], sB2[128];
    __shared__ __align__(16) float sX[67*64];
    __shared__ __align__(16) float sH[64*64];

    int t = threadIdx.x;

    if (blockIdx.x < NFPS){
        // ================= FPS role: exclusive SM, serial argmax ==========
        int b = blockIdx.x;
        int lane = t & 31, wid = t >> 5;
        const float* X = xyz + b*3*NPT;
        int base = t*8;
        float px[8],py[8],pz[8],dd[8];
        {
            float4 a0 = *(const float4*)(X + base);
            float4 a1 = *(const float4*)(X + base + 4);
            float4 b0v = *(const float4*)(X + NPT + base);
            float4 b1v = *(const float4*)(X + NPT + base + 4);
            float4 c0 = *(const float4*)(X + 2*NPT + base);
            float4 c1 = *(const float4*)(X + 2*NPT + base + 4);
            px[0]=a0.x;px[1]=a0.y;px[2]=a0.z;px[3]=a0.w;px[4]=a1.x;px[5]=a1.y;px[6]=a1.z;px[7]=a1.w;
            py[0]=b0v.x;py[1]=b0v.y;py[2]=b0v.z;py[3]=b0v.w;py[4]=b1v.x;py[5]=b1v.y;py[6]=b1v.z;py[7]=b1v.w;
            pz[0]=c0.x;pz[1]=c0.y;pz[2]=c0.z;pz[3]=c0.w;pz[4]=c1.x;pz[5]=c1.y;pz[6]=c1.z;pz[7]=c1.w;
        }
        unsigned long long px2[4],py2[4],pz2[4];
        #pragma unroll
        for (int p=0;p<4;p++){ px2[p]=pk2(px[2*p],px[2*p+1]); py2[p]=pk2(py[2*p],py[2*p+1]); pz2[p]=pk2(pz[2*p],pz[2*p+1]); }
        #pragma unroll
        for (int j=0;j<8;j++) dd[j]=1e10f;
        int f = 0;
        float cx=__ldg(X), cy=__ldg(X+NPT), cz=__ldg(X+2*NPT);
        for (int it=0; it<NQ; ++it) {
            if (t == 0) g_fps[b*NQ+it] = f;
            unsigned long long ncx=pk2(-cx,-cx), ncy=pk2(-cy,-cy), ncz=pk2(-cz,-cz);
            #pragma unroll
            for (int p=0;p<4;p++){
                // (px-cx)^2+(py-cy)^2+(pz-cz)^2, each op .rn, left-assoc (matches XLA)
                unsigned long long dx=add2(px2[p],ncx), dy=add2(py2[p],ncy), dz=add2(pz2[p],ncz);
                unsigned long long d2=add2(add2(mul2(dx,dx),mul2(dy,dy)),mul2(dz,dz));
                float dlo,dhi; upk2(d2,dlo,dhi);
                dd[2*p]   = fminf(dd[2*p],   dlo);
                dd[2*p+1] = fminf(dd[2*p+1], dhi);
            }
            float best = dd[0]; int bidx = base;
            #pragma unroll
            for (int j=1;j<8;j++) if (dd[j] > best){ best=dd[j]; bidx=base+j; }
            unsigned db   = __float_as_uint(best);        // >=0: uint order == float order
            unsigned wmax = __reduce_max_sync(FULLM, db);
            unsigned mk   = __ballot_sync(FULLM, db==wmax);
            int src = __ffs(mk)-1;                         // lowest lane = lowest index
            int par = it & 1;
            if (db==wmax && lane==src){                    // winner lane writes directly
                s_v[par][wid]=wmax; s_ix[par][wid]=(unsigned)bidx;
            }
            __syncthreads();
            unsigned vm   = s_v[par][lane & 15];
            unsigned bmax = __reduce_max_sync(FULLM, vm);
            unsigned mk2  = __ballot_sync(FULLM, vm==bmax);
            int src2 = __ffs(mk2)-1;                       // lowest warp = lowest index
            f = (int)s_ix[par][src2];
            cx=__ldg(X+f); cy=__ldg(X+NPT+f); cz=__ldg(X+2*NPT+f);   // broadcast L1 hit
            if (t==0 && (it&31)==31){
                __threadfence();                           // release g_fps publishes
                *(volatile int*)&g_prog[b] = it+1;
            }
        }
        __syncthreads();   // t0's g_fps writes visible CTA-wide (same SM L1)
        for (int i=t;i<3*NQ;i+=512){
            int c=i>>10, s=i&1023;
            out1[b*3072 + i] = X[c*NPT + g_fps[b*NQ+s]];
        }
        return;
    }

    // ==================== Worker role ====================================
    int wk = blockIdx.x - NFPS;            // 0..131
    // ---- phase A: worker0 folds weights; everyone zeroes an out2 slice ---
    if (wk == 0){
        for (int i=t;i<67*64;i+=512){int c=i>>6,o=i&63;float s=g0[o]*rsqrtf(v0[o]+1e-5f);g_W0[i]=w0[o*67+c]*s;}
        for (int i=t;i<64*64;i+=512){int c=i>>6,o=i&63;float s=g1[o]*rsqrtf(v1[o]+1e-5f);g_W1[i]=w1[o*64+c]*s;}
        for (int i=t;i<64*128;i+=512){int k=i>>7,o=i&127;float s=g2[o]*rsqrtf(v2[o]+1e-5f);g_W2[i]=w2[o*64+k]*s;}
        if (t<64){float s=g0[t]*rsqrtf(v0[t]+1e-5f);g_B0[t]=(b0[t]-m0[t])*s+be0[t];}
        if (t<64){float s=g1[t]*rsqrtf(v1[t]+1e-5f);g_B1[t]=(b1[t]-m1[t])*s+be1[t];}
        if (t<128){float s=g2[t]*rsqrtf(v2[t]+1e-5f);g_B2[t]=(b2[t]-m2[t])*s+be2[t];}
    }
    {
        float4* o4 = (float4*)out2;
        int base4 = wk*4096;
        for (int i=base4+t; i<base4+4096; i+=512)
            if (i < OUT2SZ/4) o4[i] = make_float4(0.f,0.f,0.f,0.f);
    }
    __threadfence();
    __syncthreads();
    if (t==0){
        atomicAdd(&g_zero_ctr, 1);
        if (wk==0) *(volatile int*)&g_wready = 1;
    }

    // ---- phase B: bq items, half-CTA (256 thr) each, atomic work queue ---
    {
        int hb = t >> 8, ht = t & 255;
        int wid = ht >> 5, lane = ht & 31;
        unsigned lt = (1u<<lane)-1u;
        unsigned* wbuf = ebuf[hb*8 + wid];
        for (;;){
            if (ht == 0) s_item[hb] = atomicAdd(&g_bq_ctr, 1);
            HBAR(hb+1);
            int id = s_item[hb];
            if (id >= NITEM) break;
            int ck = id >> 7, rr = id & 127, b = rr >> 3, qb = rr & 7;
            if (ht == 0) spin_ge(&g_prog[b], ck*QCH + qb*32 + 32);
            HBAR(hb+1);
            const float* Xx = xyz + b*3*NPT;
            const float* Xy = Xx + NPT;
            const float* Xz = Xx + 2*NPT;
            int s0 = ck*QCH + qb*32 + wid*4;
            float cx[4],cy[4],cz[4]; int cnt[4]={0,0,0,0}; unsigned gtag[4];
            #pragma unroll
            for (int q=0;q<4;q++){
                int s = s0+q;
                int ci = *(volatile const int*)&g_fps[b*NQ+s];  // L1-bypassing
                cx[q]=__ldg(Xx+ci); cy[q]=__ldg(Xy+ci); cz[q]=__ldg(Xz+ci);
                gtag[q]=(unsigned)(b*NQ+s)<<12;
            }
            int wn = 0;
            for (int bp=0; bp<NPT; bp+=128){
                if (cnt[0]>=NSAMP && cnt[1]>=NSAMP && cnt[2]>=NSAMP && cnt[3]>=NSAMP) break;
                int p = bp + lane*4;
                float4 fx = __ldg((const float4*)(Xx+p));
                float4 fy = __ldg((const float4*)(Xy+p));
                float4 fz = __ldg((const float4*)(Xz+p));
                float pxl[4]={fx.x,fx.y,fx.z,fx.w};
                float pyl[4]={fy.x,fy.y,fy.z,fy.w};
                float pzl[4]={fz.x,fz.y,fz.z,fz.w};
                #pragma unroll
                for (int q=0;q<4;q++){
                    if (cnt[q]>=NSAMP) continue;          // warp-uniform
                    bool inb[4]; unsigned m[4];
                    #pragma unroll
                    for (int j=0;j<4;j++){
                        float dx=pxl[j]-cx[q], dy=pyl[j]-cy[q], dz=pzl[j]-cz[q];
                        float d2=__fadd_rn(__fadd_rn(__fmul_rn(dx,dx),__fmul_rn(dy,dy)),__fmul_rn(dz,dz));
                        inb[j] = (d2 <= 0.04f);
                        m[j] = __ballot_sync(FULLM, inb[j]);
                    }
                    int tot = __popc(m[0])+__popc(m[1])+__popc(m[2])+__popc(m[3]);
                    if (!tot) continue;
                    if (cnt[q] + tot <= NSAMP){
                        int off = wn;                      // order irrelevant downstream
                        #pragma unroll
                        for (int j=0;j<4;j++){
                            if (inb[j]) wbuf[off + __popc(m[j]&lt)] = gtag[q] | (unsigned)(p+j);
                            off += __popc(m[j]);
                        }
                        wn += tot; cnt[q] += tot;
                    } else {
                        // rare: crossing NSAMP — redo this 128-chunk in index order
                        for (int sub=0; sub<4 && cnt[q]<NSAMP; ++sub){
                            int pp = bp + sub*32 + lane;
                            float dx=__ldg(Xx+pp)-cx[q], dy=__ldg(Xy+pp)-cy[q], dz=__ldg(Xz+pp)-cz[q];
                            float d2=__fadd_rn(__fadd_rn(__fmul_rn(dx,dx),__fmul_rn(dy,dy)),__fmul_rn(dz,dz));
                            bool in = (d2 <= 0.04f);
                            unsigned mask = __ballot_sync(FULLM, in);
                            int pc = __popc(mask);
                            int take = min(pc, NSAMP-cnt[q]);
                            if (in){
                                int pos = __popc(mask & lt);
                                if (pos < take) wbuf[wn+pos] = gtag[q] | (unsigned)pp;
                            }
                            wn += take; cnt[q] += take;
                        }
                    }
                }
            }
            int gb = 0;
            if (lane==0) gb = atomicAdd(&g_ecnt4[ck], wn);
            gb = __shfl_sync(FULLM, gb, 0);
            unsigned* reg = g_ent + ck*REGION;
            for (int i=lane;i<wn;i+=32) reg[gb+i] = wbuf[i];
            __threadfence();                               // each thread's stores visible
            HBAR(hb+1);                                    // all 8 warps done
            if (ht==0) atomicAdd(&g_bqdone[ck], 1);
        }
    }
    __syncthreads();   // join halves

    // ---- phase C: mlp tiles (512 thr/tile), per-chunk gated --------------
    if (t==0){
        long long g=0;
        while ((*(volatile int*)&g_zero_ctr < NWORK || *(volatile int*)&g_wready == 0)
               && g < 40000000LL){ __nanosleep(128); ++g; }
    }
    __syncthreads();
    if (t<64){ sB0[t]=g_B0[t]; sB1[t]=g_B1[t]; }
    if (t<128) sB2[t]=g_B2[t];
    int* outI = (int*)out2;
    for (int ck=0; ck<NCHUNK; ++ck){
        if (t==0) spin_ge(&g_bqdone[ck], NBATCH*8);
        __syncthreads();
        __threadfence();
        int E = *(volatile int*)&g_ecnt4[ck];
        int tiles = (E+63)>>6;
        const unsigned* ent = g_ent + ck*REGION;
        int tx = t&15, ty = t>>4;          // ty 0..31
        int le = t>>3, sub = t&7;          // gather: 8 threads/entry
        for (;;){
            __syncthreads();               // protects sX/sH + s_tl
            if (t==0) s_tl = atomicAdd(&g_mlp_ctr[ck], 1);
            __syncthreads();
            int tl = s_tl;
            if (tl >= tiles) break;
            int tbase = tl<<6;
            {   // gather 67 channels for 64 entries
                int ge = tbase + le;
                unsigned raw = ent[ge < E ? ge : 0] & 0x3FFFFFFu;
                int p = raw & 4095; int g = raw >> 12; int bb = g >> 10;
                int ci = *(volatile const int*)&g_fps[g];
                const float* pc = pts + (size_t)(bb*64)*NPT + p;
                const float* xc = xyz + (size_t)(bb*3)*NPT;
                for (int c=sub;c<67;c+=8){
                    float v;
                    if (c<3) v = __ldg(xc + c*NPT + p) - __ldg(xc + c*NPT + ci);
                    else     v = __ldg(pc + (c-3)*NPT);
                    sX[c*64+le] = v;
                }
            }
            __syncthreads();
            // ---- layer 0: 67 -> 64 (acc 4 entries x 2 channels) ----
            float a0[4][2];
            #pragma unroll
            for (int j=0;j<2;j++){ float bb=sB0[ty*2+j];
                #pragma unroll
                for (int i=0;i<4;i++) a0[i][j]=bb; }
            #pragma unroll 4
            for (int k=0;k<67;k++){
                float4 xv = *(const float4*)&sX[k*64+tx*4];
                float2 wv = __ldg((const float2*)&g_W0[k*64+ty*2]);
                float xr[4]={xv.x,xv.y,xv.z,xv.w};
                #pragma unroll
                for (int i=0;i<4;i++){ a0[i][0]=fmaf(xr[i],wv.x,a0[i][0]); a0[i][1]=fmaf(xr[i],wv.y,a0[i][1]); }
            }
            #pragma unroll
            for (int j=0;j<2;j++){
                float4 hv = make_float4(fmaxf(a0[0][j],0.f),fmaxf(a0[1][j],0.f),
                                        fmaxf(a0[2][j],0.f),fmaxf(a0[3][j],0.f));
                *(float4*)&sH[(ty*2+j)*64 + tx*4] = hv;
            }
            __syncthreads();
            // ---- layer 1: 64 -> 64 (reads sH, writes sX) ----
            float a1[4][2];
            #pragma unroll
            for (int j=0;j<2;j++){ float bb=sB1[ty*2+j];
                #pragma unroll
                for (int i=0;i<4;i++) a1[i][j]=bb; }
            #pragma unroll 4
            for (int k=0;k<64;k++){
                float4 xv = *(const float4*)&sH[k*64+tx*4];
                float2 wv = __ldg((const float2*)&g_W1[k*64+ty*2]);
                float xr[4]={xv.x,xv.y,xv.z,xv.w};
                #pragma unroll
                for (int i=0;i<4;i++){ a1[i][0]=fmaf(xr[i],wv.x,a1[i][0]); a1[i][1]=fmaf(xr[i],wv.y,a1[i][1]); }
            }
            #pragma unroll
            for (int j=0;j<2;j++){
                float4 hv = make_float4(fmaxf(a1[0][j],0.f),fmaxf(a1[1][j],0.f),
                                        fmaxf(a1[2][j],0.f),fmaxf(a1[3][j],0.f));
                *(float4*)&sX[(ty*2+j)*64 + tx*4] = hv;
            }
            __syncthreads();
            // ---- layer 2: 64 -> 128 + relu + merged atomicMax scatter ----
            float a2[4][4];
            #pragma unroll
            for (int j=0;j<4;j++){ float bb=sB2[ty*4+j];
                #pragma unroll
                for (int i=0;i<4;i++) a2[i][j]=bb; }
            #pragma unroll 4
            for (int k=0;k<64;k++){
                float4 xv = *(const float4*)&sX[k*64+tx*4];
                float4 wv = __ldg((const float4*)&g_W2[k*128+ty*4]);
                float xr[4]={xv.x,xv.y,xv.z,xv.w};
                float wr[4]={wv.x,wv.y,wv.z,wv.w};
                #pragma unroll
                for (int i=0;i<4;i++)
                    #pragma unroll
                    for (int j=0;j<4;j++) a2[i][j]=fmaf(xr[i],wr[j],a2[i][j]);
            }
            unsigned gid[4];
            #pragma unroll
            for (int i=0;i<4;i++){
                int ge = tbase + tx*4 + i;
                gid[i] = (ge < E) ? ((ent[ge] >> 12) & 0x3FFFu) : 0xFFFFFFFFu;
            }
            #pragma unroll
            for (int i=0;i<4;i++){
                if (gid[i]==0xFFFFFFFFu) continue;
                if (i>0 && gid[i]==gid[i-1]) continue;   // merged into earlier head
                float mv[4];
                #pragma unroll
                for (int j=0;j<4;j++) mv[j]=a2[i][j];
                #pragma unroll
                for (int i2=1;i2<4;i2++){
                    if (i+i2<4 && gid[i+i2]==gid[i]){
                        #pragma unroll
                        for (int j=0;j<4;j++) mv[j]=fmaxf(mv[j],a2[i+i2][j]);
                    }
                }
                int bb = gid[i]>>10, s = gid[i]&1023;
                int* po = outI + (bb*128 + ty*4)*NQ + s;
                #pragma unroll
                for (int j=0;j<4;j++)
                    atomicMax(po + j*NQ, __float_as_int(fmaxf(mv[j],0.f)));
            }
        }
    }
}

extern "C" void kernel_launch(void* const* d_in, const int* in_sizes, int n_in,
                              void* d_out, int out_size)
{
    const float* xyz = (const float*)d_in[0];
    const float* pts = (const float*)d_in[1];
    float* out1 = (float*)d_out;
    float* out2 = out1 + OUT1SZ;

    reset_kernel<<<1,32>>>();
    fused_kernel<<<NFPS+NWORK, 512>>>(xyz, pts, out1, out2,
        (const float*)d_in[2],(const float*)d_in[3],(const float*)d_in[4],
        (const float*)d_in[5],(const float*)d_in[6],(const float*)d_in[7],
        (const float*)d_in[8],(const float*)d_in[9],(const float*)d_in[10],
        (const float*)d_in[11],(const float*)d_in[12],(const float*)d_in[13],
        (const float*)d_in[14],(const float*)d_in[15],(const float*)d_in[16],
        (const float*)d_in[17],(const float*)d_in[18],(const float*)d_in[19]);
}

// round 10
// speedup vs baseline: 1.1488x; 1.1476x over previous
#include <cuda_runtime.h>

#define NBATCH 16
#define NPT    4096
#define NQ     1024
#define NSAMP  32
#define OUT1SZ (NBATCH*3*NQ)
#define OUT2SZ (NBATCH*128*NQ)
#define MAXE   (NBATCH*NQ*NSAMP + 64)
#define FULLM  0xffffffffu

__device__ int      g_fps[NBATCH*NQ];
__device__ unsigned g_ent[MAXE];
__device__ int      g_ecnt;
__device__ float    g_ptsT[NBATCH*NPT*64];   // [b][p][c] transposed points
__device__ float    g_W0[67*64], g_B0[64];
__device__ float    g_W1[64*64], g_B1[64];
__device__ float    g_W2[64*128], g_B2[128];

// ---- f32x2 packed helpers: two independent .rn fp32 ops per instruction --
__device__ __forceinline__ unsigned long long pk2(float a, float b){
    unsigned long long r; asm("mov.b64 %0,{%1,%2};":"=l"(r):"f"(a),"f"(b)); return r;
}
__device__ __forceinline__ void upk2(unsigned long long v, float&a, float&b){
    asm("mov.b64 {%0,%1},%2;":"=f"(a),"=f"(b):"l"(v));
}
__device__ __forceinline__ unsigned long long add2(unsigned long long a, unsigned long long b){
    unsigned long long r; asm("add.rn.f32x2 %0,%1,%2;":"=l"(r):"l"(a),"l"(b)); return r;
}
__device__ __forceinline__ unsigned long long mul2(unsigned long long a, unsigned long long b){
    unsigned long long r; asm("mul.rn.f32x2 %0,%1,%2;":"=l"(r):"l"(a),"l"(b)); return r;
}

// ---------------- prep: zero out2, fold BN into weights, reset counter ----
__global__ void prep_kernel(float* __restrict__ out2,
    const float* w0,const float* b0,const float* g0,const float* be0,const float* m0,const float* v0,
    const float* w1,const float* b1,const float* g1,const float* be1,const float* m1,const float* v1,
    const float* w2,const float* b2,const float* g2,const float* be2,const float* m2,const float* v2)
{
    int idx = blockIdx.x*blockDim.x + threadIdx.x;
    if (idx < OUT2SZ/4) ((float4*)out2)[idx] = make_float4(0.f,0.f,0.f,0.f);
    if (blockIdx.x == 0) {
        int t = threadIdx.x;
        if (t == 0) g_ecnt = 0;
        for (int i=t;i<67*64;i+=blockDim.x){int c=i>>6,o=i&63;float s=g0[o]*rsqrtf(v0[o]+1e-5f);g_W0[i]=w0[o*67+c]*s;}
        for (int i=t;i<64*64;i+=blockDim.x){int c=i>>6,o=i&63;float s=g1[o]*rsqrtf(v1[o]+1e-5f);g_W1[i]=w1[o*64+c]*s;}
        for (int i=t;i<64*128;i+=blockDim.x){int k=i>>7,o=i&127;float s=g2[o]*rsqrtf(v2[o]+1e-5f);g_W2[i]=w2[o*64+k]*s;}
        if (t<64){float s=g0[t]*rsqrtf(v0[t]+1e-5f);g_B0[t]=(b0[t]-m0[t])*s+be0[t];}
        if (t<64){float s=g1[t]*rsqrtf(v1[t]+1e-5f);g_B1[t]=(b1[t]-m1[t])*s+be1[t];}
        if (t<128){float s=g2[t]*rsqrtf(v2[t]+1e-5f);g_B2[t]=(b2[t]-m2[t])*s+be2[t];}
    }
}

// ---------------- transpose pts: [b][c][p] -> [b][p][c] -------------------
__global__ void __launch_bounds__(256) transpose_kernel(const float* __restrict__ pts)
{
    __shared__ float tile[64][65];
    int b = blockIdx.x >> 6, pt = blockIdx.x & 63;
    int p0 = pt*64;
    const float* src = pts + (size_t)b*64*NPT;
    for (int i=threadIdx.x; i<64*64; i+=256){
        int c = i>>6, pl = i&63;
        tile[c][pl] = src[(size_t)c*NPT + p0 + pl];
    }
    __syncthreads();
    float* dst = g_ptsT + ((size_t)b*NPT + p0)*64;
    for (int i=threadIdx.x; i<64*64; i+=256){
        int pl = i>>6, c = i&63;
        dst[(size_t)pl*64 + c] = tile[c][pl];
    }
}

// ---------------- FPS: 256 thr/CTA, 16 pts/thread, stable tree argmax -----
__global__ void __launch_bounds__(256,1) fps_kernel(const float* __restrict__ xyz,
                                                    float* __restrict__ out1)
{
    __shared__ unsigned s_v[2][8], s_ix[2][8];
    int b = blockIdx.x, t = threadIdx.x;
    int lane = t & 31, wid = t >> 5;
    const float* X = xyz + b*3*NPT;
    int base = t*16;
    float px[16],py[16],pz[16],dd[16];
    #pragma unroll
    for (int q=0;q<4;q++){
        float4 a = *(const float4*)(X + base + q*4);
        float4 bv = *(const float4*)(X + NPT + base + q*4);
        float4 c = *(const float4*)(X + 2*NPT + base + q*4);
        px[q*4]=a.x;px[q*4+1]=a.y;px[q*4+2]=a.z;px[q*4+3]=a.w;
        py[q*4]=bv.x;py[q*4+1]=bv.y;py[q*4+2]=bv.z;py[q*4+3]=bv.w;
        pz[q*4]=c.x;pz[q*4+1]=c.y;pz[q*4+2]=c.z;pz[q*4+3]=c.w;
    }
    unsigned long long px2[8],py2[8],pz2[8];
    #pragma unroll
    for (int p=0;p<8;p++){ px2[p]=pk2(px[2*p],px[2*p+1]); py2[p]=pk2(py[2*p],py[2*p+1]); pz2[p]=pk2(pz[2*p],pz[2*p+1]); }
    #pragma unroll
    for (int j=0;j<16;j++) dd[j]=1e10f;
    int f = 0;
    float cx=__ldg(X), cy=__ldg(X+NPT), cz=__ldg(X+2*NPT);
    for (int it=0; it<NQ; ++it) {
        if (t == 0) g_fps[b*NQ+it] = f;
        unsigned long long ncx=pk2(-cx,-cx), ncy=pk2(-cy,-cy), ncz=pk2(-cz,-cz);
        #pragma unroll
        for (int p=0;p<8;p++){
            // (px-cx)^2+(py-cy)^2+(pz-cz)^2, each op .rn, left-assoc (matches XLA)
            unsigned long long dx=add2(px2[p],ncx), dy=add2(py2[p],ncy), dz=add2(pz2[p],ncz);
            unsigned long long d2=add2(add2(mul2(dx,dx),mul2(dy,dy)),mul2(dz,dz));
            float dlo,dhi; upk2(d2,dlo,dhi);
            dd[2*p]   = fminf(dd[2*p],   dlo);
            dd[2*p+1] = fminf(dd[2*p+1], dhi);
        }
        // stable adjacent-pair argmax tree (ties -> lowest index, matches ref)
        float tv[8]; int tj[8];
        #pragma unroll
        for (int j=0;j<8;j++){
            bool c = dd[2*j+1] > dd[2*j];
            tv[j] = c ? dd[2*j+1] : dd[2*j];
            tj[j] = c ? 2*j+1 : 2*j;
        }
        #pragma unroll
        for (int st=4; st>=1; st>>=1){
            #pragma unroll
            for (int j=0;j<st;j++){
                bool c = tv[2*j+1] > tv[2*j];
                tv[j] = c ? tv[2*j+1] : tv[2*j];
                tj[j] = c ? tj[2*j+1] : tj[2*j];
            }
        }
        float best = tv[0]; int bidx = base + tj[0];
        unsigned db   = __float_as_uint(best);        // >=0: uint order == float order
        unsigned wmax = __reduce_max_sync(FULLM, db);
        unsigned mk   = __ballot_sync(FULLM, db==wmax);
        int src = __ffs(mk)-1;                         // lowest lane = lowest index
        int par = it & 1;
        if (db==wmax && lane==src){                    // winner lane writes directly
            s_v[par][wid]=wmax; s_ix[par][wid]=(unsigned)bidx;
        }
        __syncthreads();
        unsigned vm   = s_v[par][lane & 7];
        unsigned bmax = __reduce_max_sync(FULLM, vm);
        unsigned mk2  = __ballot_sync(FULLM, vm==bmax);
        int src2 = __ffs(mk2)-1;                       // lowest warp = lowest index
        f = (int)s_ix[par][src2];
        cx=__ldg(X+f); cy=__ldg(X+NPT+f); cz=__ldg(X+2*NPT+f);   // broadcast L1 hit
    }
    __syncthreads();
    for (int i=t;i<3*NQ;i+=256){
        int c=i>>10, s=i&1023;
        out1[b*3072 + i] = X[c*NPT + g_fps[b*NQ+s]];
    }
}

// ---------------- ball query: grid 512, 32 queries/CTA --------------------
__global__ void __launch_bounds__(256) bq_kernel(const float* __restrict__ xyz,
                                                 const float* __restrict__ out1)
{
    __shared__ unsigned ebuf[8*128];
    int b = blockIdx.x >> 5, qb = blockIdx.x & 31;
    const float* Xx = xyz + b*3*NPT;
    const float* Xy = Xx + NPT;
    const float* Xz = Xx + 2*NPT;
    int wid = threadIdx.x>>5, lane = threadIdx.x&31;
    unsigned lt = (1u<<lane)-1u;
    unsigned* wbuf = ebuf + wid*128;
    int s0 = qb*32 + wid*4;
    float cx[4],cy[4],cz[4]; int cnt[4]={0,0,0,0}; unsigned gtag[4];
    #pragma unroll
    for (int q=0;q<4;q++){
        int s = s0+q;
        cx[q]=__ldg(out1 + b*3072 + s);
        cy[q]=__ldg(out1 + b*3072 + 1024 + s);
        cz[q]=__ldg(out1 + b*3072 + 2048 + s);
        gtag[q]=(unsigned)(b*NQ+s)<<12;
    }
    int wn = 0;
    for (int bp=0; bp<NPT; bp+=128){
        if (cnt[0]>=NSAMP && cnt[1]>=NSAMP && cnt[2]>=NSAMP && cnt[3]>=NSAMP) break;
        int p = bp + lane*4;
        float4 fx = __ldg((const float4*)(Xx+p));
        float4 fy = __ldg((const float4*)(Xy+p));
        float4 fz = __ldg((const float4*)(Xz+p));
        float pxl[4]={fx.x,fx.y,fx.z,fx.w};
        float pyl[4]={fy.x,fy.y,fy.z,fy.w};
        float pzl[4]={fz.x,fz.y,fz.z,fz.w};
        #pragma unroll
        for (int q=0;q<4;q++){
            if (cnt[q]>=NSAMP) continue;          // warp-uniform
            bool inb[4]; unsigned m[4];
            #pragma unroll
            for (int j=0;j<4;j++){
                float dx=pxl[j]-cx[q], dy=pyl[j]-cy[q], dz=pzl[j]-cz[q];
                float d2=__fadd_rn(__fadd_rn(__fmul_rn(dx,dx),__fmul_rn(dy,dy)),__fmul_rn(dz,dz));
                inb[j] = (d2 <= 0.04f);
                m[j] = __ballot_sync(FULLM, inb[j]);
            }
            int tot = __popc(m[0])+__popc(m[1])+__popc(m[2])+__popc(m[3]);
            if (!tot) continue;                    // warp-uniform
            if (cnt[q] + tot <= NSAMP){
                int off = wn;                      // order irrelevant downstream
                #pragma unroll
                for (int j=0;j<4;j++){
                    if (inb[j]) wbuf[off + __popc(m[j]&lt)] = gtag[q] | (unsigned)(p+j);
                    off += __popc(m[j]);
                }
                wn += tot; cnt[q] += tot;
            } else {
                // rare: crossing NSAMP — redo this 128-chunk in index order
                for (int sub=0; sub<4 && cnt[q]<NSAMP; ++sub){
                    int pp = bp + sub*32 + lane;
                    float dx=__ldg(Xx+pp)-cx[q], dy=__ldg(Xy+pp)-cy[q], dz=__ldg(Xz+pp)-cz[q];
                    float d2=__fadd_rn(__fadd_rn(__fmul_rn(dx,dx),__fmul_rn(dy,dy)),__fmul_rn(dz,dz));
                    bool in = (d2 <= 0.04f);
                    unsigned mask = __ballot_sync(FULLM, in);
                    int pc = __popc(mask);
                    int take = min(pc, NSAMP-cnt[q]);
                    if (in){
                        int pos = __popc(mask & lt);
                        if (pos < take) wbuf[wn+pos] = gtag[q] | (unsigned)pp;
                    }
                    wn += take; cnt[q] += take;
                }
            }
        }
    }
    int gb = 0;
    if (lane==0) gb = atomicAdd(&g_ecnt, wn);
    gb = __shfl_sync(FULLM, gb, 0);
    for (int i=lane;i<wn;i+=32) g_ent[gb+i] = wbuf[i];
}

// ---------------- fused 3-layer MLP + max scatter (transposed gather) -----
__global__ void __launch_bounds__(256,3) mlp_kernel(const float* __restrict__ xyz,
                                                    float* __restrict__ out2)
{
    extern __shared__ float sm[];
    float* sX  = sm;            // 67*64 = 4288
    float* sH  = sm + 4288;     // 64*64 = 4096
    float* sB0 = sm + 8384;
    float* sB1 = sm + 8448;
    float* sB2 = sm + 8512;     // total 8640 floats = 34560 B
    int t = threadIdx.x;
    if (t<64){ sB0[t]=g_B0[t]; sB1[t]=g_B1[t]; }
    if (t<128) sB2[t]=g_B2[t];
    int E = g_ecnt;
    int tiles = (E+63)>>6;
    int tx = t&15, ty = t>>4;
    int* outI = (int*)out2;
    int le = t>>2, sub = t&3;
    for (int tb = blockIdx.x; tb < tiles; tb += gridDim.x){
        int tbase = tb<<6;
        __syncthreads();
        {   // gather 67-channel input (4 threads / entry, contiguous pts rows)
            int ge = tbase + le;
            unsigned raw = g_ent[ge < E ? ge : 0] & 0x3FFFFFFu;
            int p = raw & 4095; int g = raw >> 12; int bb = g >> 10;
            const float* pt = g_ptsT + ((size_t)(bb*NPT) + p)*64 + sub*16;
            #pragma unroll
            for (int k=0;k<4;k++){
                float4 v = __ldg((const float4*)(pt + k*4));
                int c = 3 + sub*16 + k*4;
                sX[(c  )*64+le] = v.x;
                sX[(c+1)*64+le] = v.y;
                sX[(c+2)*64+le] = v.z;
                sX[(c+3)*64+le] = v.w;
            }
            if (sub == 0){
                int ci = g_fps[g];
                const float* xc = xyz + (size_t)(bb*3)*NPT;
                #pragma unroll
                for (int c=0;c<3;c++)
                    sX[c*64+le] = __ldg(xc + c*NPT + p) - __ldg(xc + c*NPT + ci);
            }
        }
        __syncthreads();
        // ---- layer 0: 67 -> 64 ----
        float acc[4][4];
        #pragma unroll
        for (int j=0;j<4;j++){ float bb=sB0[ty*4+j];
            #pragma unroll
            for (int i=0;i<4;i++) acc[i][j]=bb; }
        #pragma unroll 4
        for (int k=0;k<67;k++){
            float4 xv = *(const float4*)&sX[k*64+tx*4];
            float4 wv = __ldg((const float4*)&g_W0[k*64+ty*4]);
            float xr[4]={xv.x,xv.y,xv.z,xv.w};
            float wr[4]={wv.x,wv.y,wv.z,wv.w};
            #pragma unroll
            for (int i=0;i<4;i++)
                #pragma unroll
                for (int j=0;j<4;j++) acc[i][j] = fmaf(xr[i],wr[j],acc[i][j]);
        }
        #pragma unroll
        for (int j=0;j<4;j++){
            float4 hv = make_float4(fmaxf(acc[0][j],0.f),fmaxf(acc[1][j],0.f),
                                    fmaxf(acc[2][j],0.f),fmaxf(acc[3][j],0.f));
            *(float4*)&sH[(ty*4+j)*64 + tx*4] = hv;
        }
        __syncthreads();
        // ---- layer 1: 64 -> 64 ----
        #pragma unroll
        for (int j=0;j<4;j++){ float bb=sB1[ty*4+j];
            #pragma unroll
            for (int i=0;i<4;i++) acc[i][j]=bb; }
        #pragma unroll 4
        for (int k=0;k<64;k++){
            float4 xv = *(const float4*)&sH[k*64+tx*4];
            float4 wv = __ldg((const float4*)&g_W1[k*64+ty*4]);
            float xr[4]={xv.x,xv.y,xv.z,xv.w};
            float wr[4]={wv.x,wv.y,wv.z,wv.w};
            #pragma unroll
            for (int i=0;i<4;i++)
                #pragma unroll
                for (int j=0;j<4;j++) acc[i][j] = fmaf(xr[i],wr[j],acc[i][j]);
        }
        #pragma unroll
        for (int j=0;j<4;j++){
            float4 hv = make_float4(fmaxf(acc[0][j],0.f),fmaxf(acc[1][j],0.f),
                                    fmaxf(acc[2][j],0.f),fmaxf(acc[3][j],0.f));
            *(float4*)&sX[(ty*4+j)*64 + tx*4] = hv;
        }
        __syncthreads();
        // ---- layer 2: 64 -> 128 + relu + merged atomicMax scatter ----
        float a2[4][8];
        #pragma unroll
        for (int j=0;j<8;j++){ float bb=sB2[ty*8+j];
            #pragma unroll
            for (int i=0;i<4;i++) a2[i][j]=bb; }
        #pragma unroll 2
        for (int k=0;k<64;k++){
            float4 xv = *(const float4*)&sX[k*64+tx*4];
            float4 wa = __ldg((const float4*)&g_W2[k*128+ty*8]);
            float4 wb = __ldg((const float4*)&g_W2[k*128+ty*8+4]);
            float xr[4]={xv.x,xv.y,xv.z,xv.w};
            float wr[8]={wa.x,wa.y,wa.z,wa.w,wb.x,wb.y,wb.z,wb.w};
            #pragma unroll
            for (int i=0;i<4;i++)
                #pragma unroll
                for (int j=0;j<8;j++) a2[i][j]=fmaf(xr[i],wr[j],a2[i][j]);
        }
        unsigned gid[4];
        #pragma unroll
        for (int i=0;i<4;i++){
            int ge = tbase + tx*4 + i;
            gid[i] = (ge < E) ? ((g_ent[ge] >> 12) & 0x3FFFu) : 0xFFFFFFFFu;
        }
        #pragma unroll
        for (int i=0;i<4;i++){
            if (gid[i]==0xFFFFFFFFu) continue;
            if (i>0 && gid[i]==gid[i-1]) continue;
            float mv[8];
            #pragma unroll
            for (int j=0;j<8;j++) mv[j]=a2[i][j];
            #pragma unroll
            for (int i2=1;i2<4;i2++){
                if (i+i2<4 && gid[i+i2]==gid[i]){
                    #pragma unroll
                    for (int j=0;j<8;j++) mv[j]=fmaxf(mv[j],a2[i+i2][j]);
                }
            }
            int bb = gid[i]>>10, s = gid[i]&1023;
            int* po = outI + (bb*128 + ty*8)*NQ + s;
            #pragma unroll
            for (int j=0;j<8;j++)
                atomicMax(po + j*NQ, __float_as_int(fmaxf(mv[j],0.f)));
        }
    }
}

extern "C" void kernel_launch(void* const* d_in, const int* in_sizes, int n_in,
                              void* d_out, int out_size)
{
    const float* xyz = (const float*)d_in[0];
    const float* pts = (const float*)d_in[1];
    float* out1 = (float*)d_out;
    float* out2 = out1 + OUT1SZ;

    prep_kernel<<<2048,256>>>(out2,
        (const float*)d_in[2],(const float*)d_in[3],(const float*)d_in[4],
        (const float*)d_in[5],(const float*)d_in[6],(const float*)d_in[7],
        (const float*)d_in[8],(const float*)d_in[9],(const float*)d_in[10],
        (const float*)d_in[11],(const float*)d_in[12],(const float*)d_in[13],
        (const float*)d_in[14],(const float*)d_in[15],(const float*)d_in[16],
        (const float*)d_in[17],(const float*)d_in[18],(const float*)d_in[19]);
    transpose_kernel<<<1024,256>>>(pts);
    fps_kernel<<<16,256>>>(xyz, out1);
    bq_kernel<<<512,256>>>(xyz, out1);
    mlp_kernel<<<592,256,34560>>>(xyz, out2);
}

// round 11
// speedup vs baseline: 1.1792x; 1.0265x over previous
#include <cuda_runtime.h>

#define NBATCH 16
#define NPT    4096
#define NQ     1024
#define NSAMP  32
#define OUT1SZ (NBATCH*3*NQ)
#define OUT2SZ (NBATCH*128*NQ)
#define MAXE   (NBATCH*NQ*NSAMP + 64)
#define FULLM  0xffffffffu

__device__ int      g_fps[NBATCH*NQ];
__device__ unsigned g_ent[MAXE];
__device__ int      g_ecnt;
__device__ float    g_ptsT[NBATCH*NPT*64];   // [b][p][c] transposed points
__device__ float    g_W0[67*64], g_B0[64];
__device__ float    g_W1[64*64], g_B1[64];
__device__ float    g_W2[64*128], g_B2[128];

// ---- f32x2 packed helpers: two independent .rn fp32 ops per instruction --
__device__ __forceinline__ unsigned long long pk2(float a, float b){
    unsigned long long r; asm("mov.b64 %0,{%1,%2};":"=l"(r):"f"(a),"f"(b)); return r;
}
__device__ __forceinline__ void upk2(unsigned long long v, float&a, float&b){
    asm("mov.b64 {%0,%1},%2;":"=f"(a),"=f"(b):"l"(v));
}
__device__ __forceinline__ unsigned long long add2(unsigned long long a, unsigned long long b){
    unsigned long long r; asm("add.rn.f32x2 %0,%1,%2;":"=l"(r):"l"(a),"l"(b)); return r;
}
__device__ __forceinline__ unsigned long long mul2(unsigned long long a, unsigned long long b){
    unsigned long long r; asm("mul.rn.f32x2 %0,%1,%2;":"=l"(r):"l"(a),"l"(b)); return r;
}

// ---------------- prep: zero out2 + fold BN + transpose pts ---------------
__global__ void __launch_bounds__(256) prep_kernel(float* __restrict__ out2,
    const float* __restrict__ pts,
    const float* w0,const float* b0,const float* g0,const float* be0,const float* m0,const float* v0,
    const float* w1,const float* b1,const float* g1,const float* be1,const float* m1,const float* v1,
    const float* w2,const float* b2,const float* g2,const float* be2,const float* m2,const float* v2)
{
    __shared__ float tile[64][65];
    int idx = blockIdx.x*blockDim.x + threadIdx.x;
    if (idx < OUT2SZ/4) ((float4*)out2)[idx] = make_float4(0.f,0.f,0.f,0.f);
    if (blockIdx.x == 0) {
        int t = threadIdx.x;
        if (t == 0) g_ecnt = 0;
        for (int i=t;i<67*64;i+=blockDim.x){int c=i>>6,o=i&63;float s=g0[o]*rsqrtf(v0[o]+1e-5f);g_W0[i]=w0[o*67+c]*s;}
        for (int i=t;i<64*64;i+=blockDim.x){int c=i>>6,o=i&63;float s=g1[o]*rsqrtf(v1[o]+1e-5f);g_W1[i]=w1[o*64+c]*s;}
        for (int i=t;i<64*128;i+=blockDim.x){int k=i>>7,o=i&127;float s=g2[o]*rsqrtf(v2[o]+1e-5f);g_W2[i]=w2[o*64+k]*s;}
        if (t<64){float s=g0[t]*rsqrtf(v0[t]+1e-5f);g_B0[t]=(b0[t]-m0[t])*s+be0[t];}
        if (t<64){float s=g1[t]*rsqrtf(v1[t]+1e-5f);g_B1[t]=(b1[t]-m1[t])*s+be1[t];}
        if (t<128){float s=g2[t]*rsqrtf(v2[t]+1e-5f);g_B2[t]=(b2[t]-m2[t])*s+be2[t];}
    }
    // transpose: CTAs 0..1023 each handle one [64ch x 64pt] tile
    if (blockIdx.x < 1024){
        int b = blockIdx.x >> 6, pt = blockIdx.x & 63;
        int p0 = pt*64;
        const float* src = pts + (size_t)b*64*NPT;
        for (int i=threadIdx.x; i<64*64; i+=256){
            int c = i>>6, pl = i&63;
            tile[c][pl] = src[(size_t)c*NPT + p0 + pl];
        }
        __syncthreads();
        float* dst = g_ptsT + ((size_t)b*NPT + p0)*64;
        for (int i=threadIdx.x; i<64*64; i+=256){
            int pl = i>>6, c = i&63;
            dst[(size_t)pl*64 + c] = tile[c][pl];
        }
    }
}

// ---------------- FPS: 256 thr/CTA, 16 pts/thread, stable tree argmax -----
__global__ void __launch_bounds__(256,1) fps_kernel(const float* __restrict__ xyz,
                                                    float* __restrict__ out1)
{
    __shared__ unsigned s_v[2][8], s_ix[2][8];
    int b = blockIdx.x, t = threadIdx.x;
    int lane = t & 31, wid = t >> 5;
    const float* X = xyz + b*3*NPT;
    int base = t*16;
    float px[16],py[16],pz[16],dd[16];
    #pragma unroll
    for (int q=0;q<4;q++){
        float4 a = *(const float4*)(X + base + q*4);
        float4 bv = *(const float4*)(X + NPT + base + q*4);
        float4 c = *(const float4*)(X + 2*NPT + base + q*4);
        px[q*4]=a.x;px[q*4+1]=a.y;px[q*4+2]=a.z;px[q*4+3]=a.w;
        py[q*4]=bv.x;py[q*4+1]=bv.y;py[q*4+2]=bv.z;py[q*4+3]=bv.w;
        pz[q*4]=c.x;pz[q*4+1]=c.y;pz[q*4+2]=c.z;pz[q*4+3]=c.w;
    }
    unsigned long long px2[8],py2[8],pz2[8];
    #pragma unroll
    for (int p=0;p<8;p++){ px2[p]=pk2(px[2*p],px[2*p+1]); py2[p]=pk2(py[2*p],py[2*p+1]); pz2[p]=pk2(pz[2*p],pz[2*p+1]); }
    #pragma unroll
    for (int j=0;j<16;j++) dd[j]=1e10f;
    int f = 0;
    float cx=__ldg(X), cy=__ldg(X+NPT), cz=__ldg(X+2*NPT);
    for (int it=0; it<NQ; ++it) {
        if (t == 0) g_fps[b*NQ+it] = f;
        unsigned long long ncx=pk2(-cx,-cx), ncy=pk2(-cy,-cy), ncz=pk2(-cz,-cz);
        #pragma unroll
        for (int p=0;p<8;p++){
            // (px-cx)^2+(py-cy)^2+(pz-cz)^2, each op .rn, left-assoc (matches XLA)
            unsigned long long dx=add2(px2[p],ncx), dy=add2(py2[p],ncy), dz=add2(pz2[p],ncz);
            unsigned long long d2=add2(add2(mul2(dx,dx),mul2(dy,dy)),mul2(dz,dz));
            float dlo,dhi; upk2(d2,dlo,dhi);
            dd[2*p]   = fminf(dd[2*p],   dlo);
            dd[2*p+1] = fminf(dd[2*p+1], dhi);
        }
        // stable adjacent-pair argmax tree (ties -> lowest index, matches ref)
        float tv[8]; int tj[8];
        #pragma unroll
        for (int j=0;j<8;j++){
            bool c = dd[2*j+1] > dd[2*j];
            tv[j] = c ? dd[2*j+1] : dd[2*j];
            tj[j] = c ? 2*j+1 : 2*j;
        }
        #pragma unroll
        for (int st=4; st>=1; st>>=1){
            #pragma unroll
            for (int j=0;j<st;j++){
                bool c = tv[2*j+1] > tv[2*j];
                tv[j] = c ? tv[2*j+1] : tv[2*j];
                tj[j] = c ? tj[2*j+1] : tj[2*j];
            }
        }
        float best = tv[0]; int bidx = base + tj[0];
        unsigned db   = __float_as_uint(best);        // >=0: uint order == float order
        unsigned wmax = __reduce_max_sync(FULLM, db);
        unsigned mk   = __ballot_sync(FULLM, db==wmax);
        int src = __ffs(mk)-1;                         // lowest lane = lowest index
        int par = it & 1;
        if (db==wmax && lane==src){                    // winner lane writes directly
            s_v[par][wid]=wmax; s_ix[par][wid]=(unsigned)bidx;
        }
        __syncthreads();
        unsigned vm   = s_v[par][lane & 7];
        unsigned bmax = __reduce_max_sync(FULLM, vm);
        unsigned mk2  = __ballot_sync(FULLM, vm==bmax);
        int src2 = __ffs(mk2)-1;                       // lowest warp = lowest index
        f = (int)s_ix[par][src2];
        cx=__ldg(X+f); cy=__ldg(X+NPT+f); cz=__ldg(X+2*NPT+f);   // broadcast L1 hit
    }
    __syncthreads();
    for (int i=t;i<3*NQ;i+=256){
        int c=i>>10, s=i&1023;
        out1[b*3072 + i] = X[c*NPT + g_fps[b*NQ+s]];
    }
}

// ---------------- ball query: packed f32x2 distance eval ------------------
__global__ void __launch_bounds__(256) bq_kernel(const float* __restrict__ xyz,
                                                 const float* __restrict__ out1)
{
    __shared__ unsigned ebuf[8*128];
    int b = blockIdx.x >> 5, qb = blockIdx.x & 31;
    const float* Xx = xyz + b*3*NPT;
    const float* Xy = Xx + NPT;
    const float* Xz = Xx + 2*NPT;
    int wid = threadIdx.x>>5, lane = threadIdx.x&31;
    unsigned lt = (1u<<lane)-1u;
    unsigned* wbuf = ebuf + wid*128;
    int s0 = qb*32 + wid*4;
    float cx[4],cy[4],cz[4]; int cnt[4]={0,0,0,0}; unsigned gtag[4];
    unsigned long long ncx[4],ncy[4],ncz[4];
    #pragma unroll
    for (int q=0;q<4;q++){
        int s = s0+q;
        cx[q]=__ldg(out1 + b*3072 + s);
        cy[q]=__ldg(out1 + b*3072 + 1024 + s);
        cz[q]=__ldg(out1 + b*3072 + 2048 + s);
        ncx[q]=pk2(-cx[q],-cx[q]); ncy[q]=pk2(-cy[q],-cy[q]); ncz[q]=pk2(-cz[q],-cz[q]);
        gtag[q]=(unsigned)(b*NQ+s)<<12;
    }
    int wn = 0;
    for (int bp=0; bp<NPT; bp+=128){
        if (cnt[0]>=NSAMP && cnt[1]>=NSAMP && cnt[2]>=NSAMP && cnt[3]>=NSAMP) break;
        int p = bp + lane*4;
        float4 fx = __ldg((const float4*)(Xx+p));
        float4 fy = __ldg((const float4*)(Xy+p));
        float4 fz = __ldg((const float4*)(Xz+p));
        unsigned long long pxa=pk2(fx.x,fx.y), pxb=pk2(fx.z,fx.w);
        unsigned long long pya=pk2(fy.x,fy.y), pyb=pk2(fy.z,fy.w);
        unsigned long long pza=pk2(fz.x,fz.y), pzb=pk2(fz.z,fz.w);
        #pragma unroll
        for (int q=0;q<4;q++){
            if (cnt[q]>=NSAMP) continue;          // warp-uniform
            // packed distance eval: bitwise identical to scalar .rn sequence
            unsigned long long dxa=add2(pxa,ncx[q]), dya=add2(pya,ncy[q]), dza=add2(pza,ncz[q]);
            unsigned long long dxb=add2(pxb,ncx[q]), dyb=add2(pyb,ncy[q]), dzb=add2(pzb,ncz[q]);
            unsigned long long sa=add2(add2(mul2(dxa,dxa),mul2(dya,dya)),mul2(dza,dza));
            unsigned long long sb=add2(add2(mul2(dxb,dxb),mul2(dyb,dyb)),mul2(dzb,dzb));
            float d0,d1,d2,d3; upk2(sa,d0,d1); upk2(sb,d2,d3);
            bool inb[4] = { d0<=0.04f, d1<=0.04f, d2<=0.04f, d3<=0.04f };
            unsigned m[4];
            #pragma unroll
            for (int j=0;j<4;j++) m[j] = __ballot_sync(FULLM, inb[j]);
            int tot = __popc(m[0])+__popc(m[1])+__popc(m[2])+__popc(m[3]);
            if (!tot) continue;                    // warp-uniform
            if (cnt[q] + tot <= NSAMP){
                int off = wn;                      // order irrelevant downstream
                #pragma unroll
                for (int j=0;j<4;j++){
                    if (inb[j]) wbuf[off + __popc(m[j]&lt)] = gtag[q] | (unsigned)(p+j);
                    off += __popc(m[j]);
                }
                wn += tot; cnt[q] += tot;
            } else {
                // rare: crossing NSAMP — redo this 128-chunk in index order
                for (int sub=0; sub<4 && cnt[q]<NSAMP; ++sub){
                    int pp = bp + sub*32 + lane;
                    float dx=__ldg(Xx+pp)-cx[q], dy=__ldg(Xy+pp)-cy[q], dz=__ldg(Xz+pp)-cz[q];
                    float dsq = __fadd_rn(__fadd_rn(__fmul_rn(dx,dx),__fmul_rn(dy,dy)),__fmul_rn(dz,dz));
                    bool in = (dsq <= 0.04f);
                    unsigned mask = __ballot_sync(FULLM, in);
                    int pc = __popc(mask);
                    int take = min(pc, NSAMP-cnt[q]);
                    if (in){
                        int pos = __popc(mask & lt);
                        if (pos < take) wbuf[wn+pos] = gtag[q] | (unsigned)pp;
                    }
                    wn += take; cnt[q] += take;
                }
            }
        }
    }
    int gb = 0;
    if (lane==0) gb = atomicAdd(&g_ecnt, wn);
    gb = __shfl_sync(FULLM, gb, 0);
    for (int i=lane;i<wn;i+=32) g_ent[gb+i] = wbuf[i];
}

// ---------------- fused 3-layer MLP + max scatter (transposed gather) -----
__global__ void __launch_bounds__(256,3) mlp_kernel(const float* __restrict__ xyz,
                                                    float* __restrict__ out2)
{
    extern __shared__ float sm[];
    float* sX  = sm;            // 67*64 = 4288
    float* sH  = sm + 4288;     // 64*64 = 4096
    float* sB0 = sm + 8384;
    float* sB1 = sm + 8448;
    float* sB2 = sm + 8512;     // total 8640 floats = 34560 B
    int t = threadIdx.x;
    if (t<64){ sB0[t]=g_B0[t]; sB1[t]=g_B1[t]; }
    if (t<128) sB2[t]=g_B2[t];
    int E = g_ecnt;
    int tiles = (E+63)>>6;
    int tx = t&15, ty = t>>4;
    int* outI = (int*)out2;
    int le = t>>2, sub = t&3;
    for (int tb = blockIdx.x; tb < tiles; tb += gridDim.x){
        int tbase = tb<<6;
        __syncthreads();
        {   // gather 67-channel input (4 threads / entry, contiguous pts rows)
            int ge = tbase + le;
            unsigned raw = g_ent[ge < E ? ge : 0] & 0x3FFFFFFu;
            int p = raw & 4095; int g = raw >> 12; int bb = g >> 10;
            const float* pt = g_ptsT + ((size_t)(bb*NPT) + p)*64 + sub*16;
            #pragma unroll
            for (int k=0;k<4;k++){
                float4 v = __ldg((const float4*)(pt + k*4));
                int c = 3 + sub*16 + k*4;
                sX[(c  )*64+le] = v.x;
                sX[(c+1)*64+le] = v.y;
                sX[(c+2)*64+le] = v.z;
                sX[(c+3)*64+le] = v.w;
            }
            if (sub == 0){
                int ci = g_fps[g];
                const float* xc = xyz + (size_t)(bb*3)*NPT;
                #pragma unroll
                for (int c=0;c<3;c++)
                    sX[c*64+le] = __ldg(xc + c*NPT + p) - __ldg(xc + c*NPT + ci);
            }
        }
        __syncthreads();
        // ---- layer 0: 67 -> 64 ----
        float acc[4][4];
        #pragma unroll
        for (int j=0;j<4;j++){ float bb=sB0[ty*4+j];
            #pragma unroll
            for (int i=0;i<4;i++) acc[i][j]=bb; }
        #pragma unroll 4
        for (int k=0;k<67;k++){
            float4 xv = *(const float4*)&sX[k*64+tx*4];
            float4 wv = __ldg((const float4*)&g_W0[k*64+ty*4]);
            float xr[4]={xv.x,xv.y,xv.z,xv.w};
            float wr[4]={wv.x,wv.y,wv.z,wv.w};
            #pragma unroll
            for (int i=0;i<4;i++)
                #pragma unroll
                for (int j=0;j<4;j++) acc[i][j] = fmaf(xr[i],wr[j],acc[i][j]);
        }
        #pragma unroll
        for (int j=0;j<4;j++){
            float4 hv = make_float4(fmaxf(acc[0][j],0.f),fmaxf(acc[1][j],0.f),
                                    fmaxf(acc[2][j],0.f),fmaxf(acc[3][j],0.f));
            *(float4*)&sH[(ty*4+j)*64 + tx*4] = hv;
        }
        __syncthreads();
        // ---- layer 1: 64 -> 64 ----
        #pragma unroll
        for (int j=0;j<4;j++){ float bb=sB1[ty*4+j];
            #pragma unroll
            for (int i=0;i<4;i++) acc[i][j]=bb; }
        #pragma unroll 4
        for (int k=0;k<64;k++){
            float4 xv = *(const float4*)&sH[k*64+tx*4];
            float4 wv = __ldg((const float4*)&g_W1[k*64+ty*4]);
            float xr[4]={xv.x,xv.y,xv.z,xv.w};
            float wr[4]={wv.x,wv.y,wv.z,wv.w};
            #pragma unroll
            for (int i=0;i<4;i++)
                #pragma unroll
                for (int j=0;j<4;j++) acc[i][j] = fmaf(xr[i],wr[j],acc[i][j]);
        }
        #pragma unroll
        for (int j=0;j<4;j++){
            float4 hv = make_float4(fmaxf(acc[0][j],0.f),fmaxf(acc[1][j],0.f),
                                    fmaxf(acc[2][j],0.f),fmaxf(acc[3][j],0.f));
            *(float4*)&sX[(ty*4+j)*64 + tx*4] = hv;
        }
        __syncthreads();
        // ---- layer 2: 64 -> 128 + relu + merged atomicMax scatter ----
        float a2[4][8];
        #pragma unroll
        for (int j=0;j<8;j++){ float bb=sB2[ty*8+j];
            #pragma unroll
            for (int i=0;i<4;i++) a2[i][j]=bb; }
        #pragma unroll 2
        for (int k=0;k<64;k++){
            float4 xv = *(const float4*)&sX[k*64+tx*4];
            float4 wa = __ldg((const float4*)&g_W2[k*128+ty*8]);
            float4 wb = __ldg((const float4*)&g_W2[k*128+ty*8+4]);
            float xr[4]={xv.x,xv.y,xv.z,xv.w};
            float wr[8]={wa.x,wa.y,wa.z,wa.w,wb.x,wb.y,wb.z,wb.w};
            #pragma unroll
            for (int i=0;i<4;i++)
                #pragma unroll
                for (int j=0;j<8;j++) a2[i][j]=fmaf(xr[i],wr[j],a2[i][j]);
        }
        unsigned gid[4];
        #pragma unroll
        for (int i=0;i<4;i++){
            int ge = tbase + tx*4 + i;
            gid[i] = (ge < E) ? ((g_ent[ge] >> 12) & 0x3FFFu) : 0xFFFFFFFFu;
        }
        #pragma unroll
        for (int i=0;i<4;i++){
            if (gid[i]==0xFFFFFFFFu) continue;
            if (i>0 && gid[i]==gid[i-1]) continue;
            float mv[8];
            #pragma unroll
            for (int j=0;j<8;j++) mv[j]=a2[i][j];
            #pragma unroll
            for (int i2=1;i2<4;i2++){
                if (i+i2<4 && gid[i+i2]==gid[i]){
                    #pragma unroll
                    for (int j=0;j<8;j++) mv[j]=fmaxf(mv[j],a2[i+i2][j]);
                }
            }
            int bb = gid[i]>>10, s = gid[i]&1023;
            int* po = outI + (bb*128 + ty*8)*NQ + s;
            #pragma unroll
            for (int j=0;j<8;j++)
                atomicMax(po + j*NQ, __float_as_int(fmaxf(mv[j],0.f)));
        }
    }
}

extern "C" void kernel_launch(void* const* d_in, const int* in_sizes, int n_in,
                              void* d_out, int out_size)
{
    const float* xyz = (const float*)d_in[0];
    const float* pts = (const float*)d_in[1];
    float* out1 = (float*)d_out;
    float* out2 = out1 + OUT1SZ;

    prep_kernel<<<2048,256>>>(out2, pts,
        (const float*)d_in[2],(const float*)d_in[3],(const float*)d_in[4],
        (const float*)d_in[5],(const float*)d_in[6],(const float*)d_in[7],
        (const float*)d_in[8],(const float*)d_in[9],(const float*)d_in[10],
        (const float*)d_in[11],(const float*)d_in[12],(const float*)d_in[13],
        (const float*)d_in[14],(const float*)d_in[15],(const float*)d_in[16],
        (const float*)d_in[17],(const float*)d_in[18],(const float*)d_in[19]);
    fps_kernel<<<16,256>>>(xyz, out1);
    bq_kernel<<<512,256>>>(xyz, out1);
    mlp_kernel<<<592,256,34560>>>(xyz, out2);
}